// round 16
// baseline (speedup 1.0000x reference)
#include <cuda_runtime.h>
#include <cuda_fp16.h>
#include <cstdint>

#define Nn 8
#define Cc 128
#define Ll 1024
#define Kk 100
#define EPSf 1e-8f

#define PRODUCERS 512   // 16 (2N) tensor-halves x 32 tiles
#define CONSUMERS 512   // 16 warps each -> 8192 rows

// Normalized fp16 rows, [N, L, C] (256B per row).
// c rows are scaled by 2/norm (INV_TEMP folded in); z rows by 1/norm.
__device__ __half g_zh[Nn * Ll * Cc];
__device__ __half g_ch[Nn * Ll * Cc];
// Producer-done counter + consumer reset ticket (zero-initialized at load;
// invariant restored by the last consumer each launch -> graph-replay safe).
__device__ int g_ctr;
__device__ int g_done;

__global__ void __launch_bounds__(512, 4) fused_k(const float* __restrict__ zsrc,
                                                  const float* __restrict__ csrc,
                                                  const int* __restrict__ neg_inds,
                                                  float* __restrict__ out) {
    __shared__ float tile[32][129];
    __shared__ float sp[16][32];
    __shared__ float srn[32];
    __shared__ int   sidx[16][108];

    int bid = blockIdx.x;
    int tid = threadIdx.x;

    if (bid < PRODUCERS) {
        // ---------------- producer: prep one 32t x 128ch tile ----------------
        int zz = bid >> 5;              // 0..15
        bool is_c = zz >= Nn;
        int n = is_c ? zz - Nn : zz;
        int ld      = is_c ? (Ll + 1) : Ll;
        int col_off = is_c ? 1 : 0;
        int t0 = (bid & 31) * 32;
        const float* s = (is_c ? csrc : zsrc) + (size_t)n * Cc * ld + col_off + t0;
        __half* d = (is_c ? g_ch : g_zh) + ((size_t)n * Ll + t0) * Cc;
        float nscale = is_c ? 2.0f : 1.0f;   // fold 1/TEMP into c

        int tx = tid & 31;    // t within tile
        int ty = tid >> 5;    // 0..15

        float acc = 0.f;
#pragma unroll
        for (int i = 0; i < 8; i++) {
            int ch = i * 16 + ty;
            float v = s[(size_t)ch * ld + tx];
            tile[tx][ch] = v;
            acc += v * v;
        }
        sp[ty][tx] = acc;
        __syncthreads();

        if (tid < 32) {
            float sum = 0.f;
#pragma unroll
            for (int y = 0; y < 16; y++) sum += sp[y][tid];
            srn[tid] = nscale / fmaxf(sqrtf(sum), EPSf);
        }
        __syncthreads();

        {
            int t = tid >> 4;
            int k = tid & 15;
            float rn = srn[t];
            __half2 h[4];
#pragma unroll
            for (int q = 0; q < 4; q++) {
                float a = tile[t][k * 8 + 2 * q]     * rn;
                float b = tile[t][k * 8 + 2 * q + 1] * rn;
                h[q] = __floats2half2_rn(a, b);
            }
            ((uint4*)(d + (size_t)t * Cc))[k] = *(const uint4*)h;
        }

        // Signal: all stores of this block done -> count one producer.
        __syncthreads();
        if (tid == 0) {
            __threadfence();
            atomicAdd(&g_ctr, 1);
        }
        return;
    }

    // ------------------- consumer: 16 warp-rows per block -------------------
    int mb   = bid - PRODUCERS;            // 0..511
    int warp = tid >> 5;                   // 0..15
    int r    = (mb << 4) + warp;           // 0..8191
    int n    = r >> 10;
    int t    = r & (Ll - 1);
    int lane = tid & 31;
    int g    = lane >> 3;                  // dot slot within pass
    int p    = lane & 7;                   // lane within dot

    // Stage indices NOW (independent of prep): slot 0 = t, 1..100 = negs.
    const int* ni = neg_inds + (size_t)r * Kk;
    int* si = sidx[warp];
#pragma unroll
    for (int i = 0; i < 4; i++) {
        int jj = lane + 32 * i;            // 0..127
        if (jj < 108) si[jj] = (jj >= 1 && jj <= Kk) ? ni[jj - 1] : t;
    }

    // Wait for all producers.
    if (tid == 0) {
        while (((volatile int*)&g_ctr)[0] < PRODUCERS) { }
        __threadfence();
    }
    __syncthreads();

    // c chunk: 16 channels for this lane (slots p and 8+p), kept as half2.
    const uint4* crow = (const uint4*)(g_ch + (size_t)r * Cc);
    uint4 ca = crow[p], cb = crow[8 + p];
    __half2 ch2[8];
    {
        const __half2* h = (const __half2*)&ca;
        ch2[0] = h[0]; ch2[1] = h[1]; ch2[2] = h[2]; ch2[3] = h[3];
        h = (const __half2*)&cb;
        ch2[4] = h[0]; ch2[5] = h[1]; ch2[6] = h[2]; ch2[7] = h[3];
    }

    const uint4* zbase = (const uint4*)(g_zh + ((size_t)n << 10) * Cc);
    float*       orow  = out + (size_t)r * (Kk + 1);

    // Prologue: z for pass 0; index register for pass 1's prefetch.
    int ia = si[g];
    uint4 z0a = zbase[(size_t)ia * 16 + p];
    uint4 z0b = zbase[(size_t)ia * 16 + 8 + p];
    int inext = si[4 + g];

#pragma unroll
    for (int pass = 0; pass < 26; pass++) {
        int j = pass * 4 + g;

        // Prefetch z for pass+1 (index already resident); LDS index for pass+2.
        uint4 ya, yb;
        if (pass < 25) {
            ya = zbase[(size_t)inext * 16 + p];
            yb = zbase[(size_t)inext * 16 + 8 + p];
        }
        if (pass < 24) inext = si[j + 8];

        // 16 products via 8 HFMA2 across two independent accumulators.
        __half2 acc0 = __floats2half2_rn(0.f, 0.f);
        __half2 acc1 = __floats2half2_rn(0.f, 0.f);
        {
            const __half2* zh = (const __half2*)&z0a;
            acc0 = __hfma2(ch2[0], zh[0], acc0);
            acc1 = __hfma2(ch2[1], zh[1], acc1);
            acc0 = __hfma2(ch2[2], zh[2], acc0);
            acc1 = __hfma2(ch2[3], zh[3], acc1);
            zh = (const __half2*)&z0b;
            acc0 = __hfma2(ch2[4], zh[0], acc0);
            acc1 = __hfma2(ch2[5], zh[1], acc1);
            acc0 = __hfma2(ch2[6], zh[2], acc0);
            acc1 = __hfma2(ch2[7], zh[3], acc1);
        }
        float2 f0 = __half22float2(acc0);
        float2 f1 = __half22float2(acc1);
        float a = (f0.x + f0.y) + (f1.x + f1.y);

        a += __shfl_xor_sync(0xffffffffu, a, 1);
        a += __shfl_xor_sync(0xffffffffu, a, 2);
        a += __shfl_xor_sync(0xffffffffu, a, 4);

        if (p == 0 && j <= Kk)
            orow[j] = a;          // norms and 1/TEMP all folded into prep

        z0a = ya; z0b = yb;
    }

    // Reset counters for the next graph replay (last consumer block).
    __syncthreads();
    if (tid == 0) {
        int k = atomicAdd(&g_done, 1);
        if (k == CONSUMERS - 1) {
            g_ctr  = 0;
            g_done = 0;
        }
    }
}

extern "C" void kernel_launch(void* const* d_in, const int* in_sizes, int n_in,
                              void* d_out, int out_size) {
    const float* z  = (const float*)d_in[0];  // [N, C, L]
    const float* c  = (const float*)d_in[1];  // [N, C, L+1]
    const int*   ni = (const int*)d_in[2];    // [N, L, K]
    float* out = (float*)d_out;               // [N*L, K+1]

    fused_k<<<PRODUCERS + CONSUMERS, 512>>>(z, c, ni, out);
}

// round 17
// speedup vs baseline: 1.1753x; 1.1753x over previous
#include <cuda_runtime.h>
#include <cuda_fp16.h>
#include <cstdint>

#define Nn 8
#define Cc 128
#define Ll 1024
#define Kk 100
#define EPSf 1e-8f

// Normalized fp16 rows, [N, L, C] (256B per row).
// c rows are scaled by 2/norm (INV_TEMP folded in); z rows by 1/norm.
__device__ __half g_zh[Nn * Ll * Cc];
__device__ __half g_ch[Nn * Ll * Cc];

// Fused: transpose + norm + normalize (+temp fold for c) + fp16 convert.
// 512 threads per 32t x 128ch tile; full 128B load segments over t.
__global__ void __launch_bounds__(512) prep_k(const float* __restrict__ zsrc,
                                              const float* __restrict__ csrc) {
    __shared__ float tile[32][129];
    __shared__ float sp[16][32];
    __shared__ float srn[32];

    int zz = blockIdx.y;
    bool is_c = zz >= Nn;
    int n = is_c ? zz - Nn : zz;
    int ld      = is_c ? (Ll + 1) : Ll;
    int col_off = is_c ? 1 : 0;
    int t0 = blockIdx.x * 32;
    const float* s = (is_c ? csrc : zsrc) + (size_t)n * Cc * ld + col_off + t0;
    __half* d = (is_c ? g_ch : g_zh) + ((size_t)n * Ll + t0) * Cc;
    float nscale = is_c ? 2.0f : 1.0f;     // fold 1/TEMP into c

    int tid = threadIdx.x;
    int tx  = tid & 31;    // t within tile
    int ty  = tid >> 5;    // 0..15

    float acc = 0.f;
#pragma unroll
    for (int i = 0; i < 8; i++) {
        int ch = i * 16 + ty;
        float v = s[(size_t)ch * ld + tx];
        tile[tx][ch] = v;
        acc += v * v;
    }
    sp[ty][tx] = acc;
    __syncthreads();

    if (tid < 32) {
        float sum = 0.f;
#pragma unroll
        for (int y = 0; y < 16; y++) sum += sp[y][tid];
        srn[tid] = nscale / fmaxf(sqrtf(sum), EPSf);
    }
    __syncthreads();

    // Write: 32 rows x 16 uint4 = 512 uint4; one per thread, coalesced.
    {
        int t = tid >> 4;
        int k = tid & 15;
        float rn = srn[t];
        __half2 h[4];
#pragma unroll
        for (int q = 0; q < 4; q++) {
            float a = tile[t][k * 8 + 2 * q]     * rn;
            float b = tile[t][k * 8 + 2 * q + 1] * rn;
            h[q] = __floats2half2_rn(a, b);
        }
        ((uint4*)(d + (size_t)t * Cc))[k] = *(const uint4*)h;
    }
}

// Warp-per-row, 8 warps/block (verified best config: depth-2 z buffer,
// smem-staged indices, HFMA2 dual accumulators). Launched with PDL: the
// neg_inds staging overlaps prep_k's tail; cudaGridDependencySynchronize()
// gates only the reads of g_zh/g_ch.
__global__ void __launch_bounds__(256) main_k(const int* __restrict__ neg_inds,
                                              float* __restrict__ out) {
    __shared__ int sidx[8][108];

    int warp = threadIdx.x >> 5;
    int r    = (blockIdx.x << 3) + warp;   // 0..N*L-1
    int n    = r >> 10;
    int t    = r & (Ll - 1);
    int lane = threadIdx.x & 31;
    int g    = lane >> 3;                  // dot slot within pass
    int p    = lane & 7;                   // lane within dot

    // Stage indices (independent of prep): slot 0 = t, 1..100 = negatives.
    const int* ni = neg_inds + (size_t)r * Kk;
    int* si = sidx[warp];
#pragma unroll
    for (int i = 0; i < 4; i++) {
        int jj = lane + 32 * i;            // 0..127
        if (jj < 108) si[jj] = (jj >= 1 && jj <= Kk) ? ni[jj - 1] : t;
    }

    // Wait for prep_k's stores to be visible (PDL dependency point).
    cudaGridDependencySynchronize();
    __syncwarp();

    // c chunk: 16 channels for this lane (slots p and 8+p), kept as half2.
    const uint4* crow = (const uint4*)(g_ch + (size_t)r * Cc);
    uint4 ca = crow[p], cb = crow[8 + p];
    __half2 ch2[8];
    {
        const __half2* h = (const __half2*)&ca;
        ch2[0] = h[0]; ch2[1] = h[1]; ch2[2] = h[2]; ch2[3] = h[3];
        h = (const __half2*)&cb;
        ch2[4] = h[0]; ch2[5] = h[1]; ch2[6] = h[2]; ch2[7] = h[3];
    }

    const uint4* zbase = (const uint4*)(g_zh + ((size_t)n << 10) * Cc);
    float*       orow  = out + (size_t)r * (Kk + 1);

    // Prologue: z for pass 0; index register for pass 1's prefetch.
    int ia = si[g];
    uint4 z0a = zbase[(size_t)ia * 16 + p];
    uint4 z0b = zbase[(size_t)ia * 16 + 8 + p];
    int inext = si[4 + g];

#pragma unroll
    for (int pass = 0; pass < 26; pass++) {
        int j = pass * 4 + g;

        // Prefetch z for pass+1 (index already resident); LDS index for pass+2.
        uint4 ya, yb;
        if (pass < 25) {
            ya = zbase[(size_t)inext * 16 + p];
            yb = zbase[(size_t)inext * 16 + 8 + p];
        }
        if (pass < 24) inext = si[j + 8];

        // 16 products via 8 HFMA2 across two independent accumulators.
        __half2 acc0 = __floats2half2_rn(0.f, 0.f);
        __half2 acc1 = __floats2half2_rn(0.f, 0.f);
        {
            const __half2* zh = (const __half2*)&z0a;
            acc0 = __hfma2(ch2[0], zh[0], acc0);
            acc1 = __hfma2(ch2[1], zh[1], acc1);
            acc0 = __hfma2(ch2[2], zh[2], acc0);
            acc1 = __hfma2(ch2[3], zh[3], acc1);
            zh = (const __half2*)&z0b;
            acc0 = __hfma2(ch2[4], zh[0], acc0);
            acc1 = __hfma2(ch2[5], zh[1], acc1);
            acc0 = __hfma2(ch2[6], zh[2], acc0);
            acc1 = __hfma2(ch2[7], zh[3], acc1);
        }
        float2 f0 = __half22float2(acc0);
        float2 f1 = __half22float2(acc1);
        float a = (f0.x + f0.y) + (f1.x + f1.y);

        a += __shfl_xor_sync(0xffffffffu, a, 1);
        a += __shfl_xor_sync(0xffffffffu, a, 2);
        a += __shfl_xor_sync(0xffffffffu, a, 4);

        if (p == 0 && j <= Kk)
            orow[j] = a;          // norms and 1/TEMP all folded into prep

        z0a = ya; z0b = yb;
    }
}

extern "C" void kernel_launch(void* const* d_in, const int* in_sizes, int n_in,
                              void* d_out, int out_size) {
    const float* z  = (const float*)d_in[0];  // [N, C, L]
    const float* c  = (const float*)d_in[1];  // [N, C, L+1]
    const int*   ni = (const int*)d_in[2];    // [N, L, K]
    float* out = (float*)d_out;               // [N*L, K+1]

    dim3 pg(Ll / 32, 2 * Nn);
    prep_k<<<pg, 512>>>(z, c);

    // PDL launch of main_k: may begin before prep_k completes; the in-kernel
    // cudaGridDependencySynchronize() enforces the data dependency.
    cudaLaunchConfig_t cfg = {};
    cfg.gridDim  = dim3((Nn * Ll) / 8);
    cfg.blockDim = dim3(256);
    cudaLaunchAttribute attr[1];
    attr[0].id = cudaLaunchAttributeProgrammaticStreamSerialization;
    attr[0].val.programmaticStreamSerializationAllowed = 1;
    cfg.attrs = attr;
    cfg.numAttrs = 1;
    cudaLaunchKernelEx(&cfg, main_k, ni, out);
}